// round 8
// baseline (speedup 1.0000x reference)
#include <cuda_runtime.h>
#include <cuda_fp16.h>
#include <cstdint>

// MeshConvPoint: B=8, C=64, V=25000, D=12, O=64
// k1 (HMMA, pipelined): Z[b,v,o'] = sum_c x[b,c,v] * W[o,c,k], o'=k*64+o
//   2-pass fp16 split: (x_hi + x_lo) * W_hi, fp32 accumulate.
//   (W residual dropped: adds ~2.4e-4 rel err, cuts MMA work 1/3 + 18KB smem.)
//   x stored [c][v] in smem (fp16), A via ldmatrix.trans; W split once per block,
//   A double-buffered with LDG prefetch before MMA. 55.3KB smem -> 4 CTA/SM.
//   z0 (k=0) fp32; z1 (k=1) fp16 (128B rows, L2-resident).
// k2: out = z0 + (1/deg)*sum z1[nbr] + bias. Branch-free gathers (zero-row pad),
//   half2 accumulation, pre-scaled 32-bit offsets, z0 hoisted above gathers.

#define BB 8
#define CC 64
#define VV 25000
#define DD 12
#define OO 64
#define NT 391            // ceil(VV/64) v-tiles
#define GX 74             // k1 grid.x (74*8=592 blocks = 4/SM)

__device__ float  g_z0[(size_t)BB * VV * 64];          // 51.2 MB
__device__ __half g_z1[((size_t)BB * VV + 1) * 64];    // 25.6 MB + zero row (bss-zeroed, never written)

__device__ __forceinline__ uint32_t smem_u32(const void* p) {
    uint32_t a;
    asm("{ .reg .u64 t; cvta.to.shared.u64 t, %1; cvt.u32.u64 %0, t; }" : "=r"(a) : "l"(p));
    return a;
}
__device__ __forceinline__ void ldsm_x4_t(uint32_t& r0, uint32_t& r1, uint32_t& r2, uint32_t& r3,
                                          uint32_t addr) {
    asm volatile("ldmatrix.sync.aligned.m8n8.x4.trans.shared.b16 {%0,%1,%2,%3}, [%4];"
                 : "=r"(r0), "=r"(r1), "=r"(r2), "=r"(r3) : "r"(addr));
}
__device__ __forceinline__ void ldsm_x2(uint32_t& r0, uint32_t& r1, uint32_t addr) {
    asm volatile("ldmatrix.sync.aligned.m8n8.x2.shared.b16 {%0,%1}, [%2];"
                 : "=r"(r0), "=r"(r1) : "r"(addr));
}
__device__ __forceinline__ void mma16816(float* c, const uint32_t* a, const uint32_t* bfr) {
    asm volatile(
        "mma.sync.aligned.m16n8k16.row.col.f32.f16.f16.f32 "
        "{%0,%1,%2,%3}, {%4,%5,%6,%7}, {%8,%9}, {%0,%1,%2,%3};"
        : "+f"(c[0]), "+f"(c[1]), "+f"(c[2]), "+f"(c[3])
        : "r"(a[0]), "r"(a[1]), "r"(a[2]), "r"(a[3]), "r"(bfr[0]), "r"(bfr[1]));
}
__device__ __forceinline__ uint32_t packh2(__half a, __half b) {
    __half2 h = __halves2half2(a, b);
    return *reinterpret_cast<uint32_t*>(&h);
}

// smem layout (bytes), row stride 144 -> conflict-free ldmatrix
#define LDB    144
#define SM_BHI 0
#define SM_A0H (SM_BHI + 128 * LDB)       // 18432
#define SM_A0L (SM_A0H + 64 * LDB)        // 27648
#define SM_A1H (SM_A0L + 64 * LDB)        // 36864
#define SM_A1L (SM_A1H + 64 * LDB)        // 46080
#define SM_TOTAL (SM_A1L + 64 * LDB)      // 55296 -> 4 CTAs/SM

// ---------------------------------------------------------------------------
// Kernel 1: 256 threads (8 warps, warp-grid 2m x 4n). Tile = 64v x 128o'.
// Block loops over v-tiles t = bx, bx+GX, ... with double-buffered A.
// ---------------------------------------------------------------------------
__global__ __launch_bounds__(256, 4) void k1_gemm(const float* __restrict__ x,
                                                  const float* __restrict__ W) {
    extern __shared__ char smem[];
    const uint32_t sb = smem_u32(smem);
    const int tid = threadIdx.x, wid = tid >> 5, lane = tid & 31;
    const int b = blockIdx.y, bx = blockIdx.x;
    const int mh = wid >> 2, nq = wid & 3;

    // ---- W prep (once per block): hi-split only. 1024 items = 128 rows x 8 groups
    for (int i = tid; i < 1024; i += 256) {
        int op = i >> 3, g = i & 7;       // B-row o' = kk*64+o, c-group
        int o = op & 63, kk = op >> 6;
        __half hi8[8];
        #pragma unroll
        for (int cc = 0; cc < 8; cc++)
            hi8[cc] = __float2half_rn(W[((size_t)o * 64 + g * 8 + cc) * 2 + kk]);
        *reinterpret_cast<uint4*>(smem + SM_BHI + (uint32_t)op * LDB + g * 16) =
            *reinterpret_cast<uint4*>(hi8);
    }

    const float* xb = x + (size_t)b * CC * VV;
    const int c  = tid >> 2;              // x row this thread loads/converts
    const int vs = (tid & 3) * 16;        // 16 v's = 4 float4

    float4 f[4];
    {
        const int v0 = bx * 64;
        #pragma unroll
        for (int j = 0; j < 4; j++) {
            int vbse = v0 + vs + 4 * j;
            f[j] = (vbse + 3 < VV) ? *reinterpret_cast<const float4*>(xb + (size_t)c * VV + vbse)
                                   : make_float4(0.f, 0.f, 0.f, 0.f);
        }
    }
    {
        uint32_t offH = SM_A0H + (uint32_t)c * LDB + vs * 2;
        uint32_t offL = SM_A0L + (uint32_t)c * LDB + vs * 2;
        #pragma unroll
        for (int j = 0; j < 4; j++) {
            __half h0 = __float2half_rn(f[j].x), h1 = __float2half_rn(f[j].y);
            __half h2 = __float2half_rn(f[j].z), h3 = __float2half_rn(f[j].w);
            uint2 uh = make_uint2(packh2(h0, h1), packh2(h2, h3));
            uint2 ul = make_uint2(packh2(__float2half_rn(f[j].x - __half2float(h0)),
                                         __float2half_rn(f[j].y - __half2float(h1))),
                                  packh2(__float2half_rn(f[j].z - __half2float(h2)),
                                         __float2half_rn(f[j].w - __half2float(h3))));
            *reinterpret_cast<uint2*>(smem + offH + j * 8) = uh;
            *reinterpret_cast<uint2*>(smem + offL + j * 8) = ul;
        }
    }

    const int r  = lane >> 2, cp = (lane & 3) * 2;
    float*  z0p = g_z0 + (size_t)b * VV * 64;
    __half* z1p = g_z1 + (size_t)b * VV * 64;

    int buf = 0;
    for (int t = bx; t < NT; t += GX) {
        __syncthreads();                  // A[buf] (and W on iter 0) visible
        const int tn = t + GX;

        // prefetch next tile's x into regs (in flight during MMA)
        if (tn < NT) {
            const int v0n = tn * 64;
            #pragma unroll
            for (int j = 0; j < 4; j++) {
                int vbse = v0n + vs + 4 * j;
                f[j] = (vbse + 3 < VV) ? *reinterpret_cast<const float4*>(xb + (size_t)c * VV + vbse)
                                       : make_float4(0.f, 0.f, 0.f, 0.f);
            }
        }

        // ---- MMA on A[buf]: 2 passes (A_hi, A_lo) x B_hi, K=64 in 4 steps ----
        float acc[2][4][4];
        #pragma unroll
        for (int mt = 0; mt < 2; mt++)
            #pragma unroll
            for (int nt = 0; nt < 4; nt++)
                #pragma unroll
                for (int q = 0; q < 4; q++) acc[mt][nt][q] = 0.0f;

        const uint32_t AH = sb + (buf ? SM_A1H : SM_A0H);
        const uint32_t AL = sb + (buf ? SM_A1L : SM_A0L);
        #pragma unroll
        for (int pass = 0; pass < 2; pass++) {
            const uint32_t Ab = pass ? AL : AH;
            const uint32_t Bb = sb + SM_BHI;
            #pragma unroll
            for (int ks = 0; ks < 4; ks++) {
                uint32_t af[2][4];
                #pragma unroll
                for (int mt = 0; mt < 2; mt++) {
                    uint32_t r0, r1, r2, r3;
                    uint32_t addr = Ab + (ks * 16 + (lane & 15)) * LDB
                                  + (mh * 32 + mt * 16) * 2 + (lane >> 4) * 16;
                    ldsm_x4_t(r0, r1, r2, r3, addr);
                    af[mt][0] = r0; af[mt][1] = r2; af[mt][2] = r1; af[mt][3] = r3;
                }
                uint32_t bf[4][2];
                #pragma unroll
                for (int nt = 0; nt < 4; nt++) {
                    uint32_t addr = Bb + (nq * 32 + nt * 8 + (lane & 7)) * LDB
                                  + ks * 32 + ((lane >> 3) & 1) * 16;
                    ldsm_x2(bf[nt][0], bf[nt][1], addr);
                }
                #pragma unroll
                for (int mt = 0; mt < 2; mt++)
                    #pragma unroll
                    for (int nt = 0; nt < 4; nt++)
                        mma16816(acc[mt][nt], af[mt], bf[nt]);
            }
        }

        // fill other buffer with prefetched tile
        if (tn < NT) {
            uint32_t offH = (buf ? SM_A0H : SM_A1H) + (uint32_t)c * LDB + vs * 2;
            uint32_t offL = (buf ? SM_A0L : SM_A1L) + (uint32_t)c * LDB + vs * 2;
            #pragma unroll
            for (int j = 0; j < 4; j++) {
                __half h0 = __float2half_rn(f[j].x), h1 = __float2half_rn(f[j].y);
                __half h2 = __float2half_rn(f[j].z), h3 = __float2half_rn(f[j].w);
                uint2 uh = make_uint2(packh2(h0, h1), packh2(h2, h3));
                uint2 ul = make_uint2(packh2(__float2half_rn(f[j].x - __half2float(h0)),
                                             __float2half_rn(f[j].y - __half2float(h1))),
                                      packh2(__float2half_rn(f[j].z - __half2float(h2)),
                                             __float2half_rn(f[j].w - __half2float(h3))));
                *reinterpret_cast<uint2*>(smem + offH + j * 8) = uh;
                *reinterpret_cast<uint2*>(smem + offL + j * 8) = ul;
            }
        }

        // ---- epilogue: nq 0-1 -> z0 fp32, nq 2-3 -> z1 fp16 ----
        const int v0 = t * 64;
        if (nq < 2) {
            #pragma unroll
            for (int mt = 0; mt < 2; mt++) {
                int v1 = v0 + mh * 32 + mt * 16 + r;
                #pragma unroll
                for (int nt = 0; nt < 4; nt++) {
                    int op = nq * 32 + nt * 8 + cp;
                    if (v1 < VV)
                        *reinterpret_cast<float2*>(z0p + (size_t)v1 * 64 + op) =
                            make_float2(acc[mt][nt][0], acc[mt][nt][1]);
                    if (v1 + 8 < VV)
                        *reinterpret_cast<float2*>(z0p + (size_t)(v1 + 8) * 64 + op) =
                            make_float2(acc[mt][nt][2], acc[mt][nt][3]);
                }
            }
        } else {
            #pragma unroll
            for (int mt = 0; mt < 2; mt++) {
                int v1 = v0 + mh * 32 + mt * 16 + r;
                #pragma unroll
                for (int nt = 0; nt < 4; nt++) {
                    int oo = (nq - 2) * 32 + nt * 8 + cp;
                    if (v1 < VV) {
                        __half2 h = __floats2half2_rn(acc[mt][nt][0], acc[mt][nt][1]);
                        *reinterpret_cast<__half2*>(z1p + (size_t)v1 * 64 + oo) = h;
                    }
                    if (v1 + 8 < VV) {
                        __half2 h = __floats2half2_rn(acc[mt][nt][2], acc[mt][nt][3]);
                        *reinterpret_cast<__half2*>(z1p + (size_t)(v1 + 8) * 64 + oo) = h;
                    }
                }
            }
        }
        buf ^= 1;
    }
}

// ---------------------------------------------------------------------------
// Kernel 2: 32 v per block, 256 threads. Branch-free gathers (zero-row pad),
// pre-scaled 32-bit offsets, half2 accumulation, z0 hoisted above gathers.
// ---------------------------------------------------------------------------
__global__ __launch_bounds__(256) void k2_gather(const int* __restrict__ nbr,
                                                 const int* __restrict__ deg,
                                                 const float* __restrict__ bias,
                                                 float* __restrict__ out) {
    __shared__ int   rows32[32][DD];   // safe z1 row index * 32
    __shared__ int   deg_s[32];
    __shared__ float ob[64][33];

    const int b = blockIdx.y, v0 = blockIdx.x * 32, tid = threadIdx.x;

    if (tid < 32) {
        int gv = v0 + tid;
        deg_s[tid] = (gv < VV) ? deg[(size_t)b * VV + gv] : 0;
    }
    __syncthreads();
    for (int i = tid; i < 32 * DD; i += 256) {
        int v = i / DD, d = i % DD;
        int gv = v0 + v;
        int rr = BB * VV;                                 // zero row
        if (gv < VV && d < deg_s[v])
            rr = b * VV + nbr[((size_t)b * VV + gv) * DD + d];
        rows32[v][d] = rr * 32;
    }
    __syncthreads();

    const int w = tid >> 5, lane = tid & 31;
    const __half2* z1p = reinterpret_cast<const __half2*>(g_z1);
    const float2 bia = *reinterpret_cast<const float2*>(bias + 2 * lane);

    #pragma unroll
    for (int j = 0; j < 4; j++) {
        const int vl = w * 4 + j;
        const int gv = v0 + vl;
        float2 s = make_float2(0.f, 0.f);
        if (gv < VV)                                       // hoisted: latency overlaps gathers
            s = *reinterpret_cast<const float2*>(g_z0 + ((size_t)b * VV + gv) * 64 + 2 * lane);
        __half2 a = __halves2half2(__ushort_as_half(0), __ushort_as_half(0));
        #pragma unroll
        for (int d = 0; d < DD; d++) {
            int off = rows32[vl][d] + lane;               // IADD
            a = __hadd2(a, z1p[off]);                     // 128B coalesced/warp
        }
        if (gv < VV) {
            float2 af = __half22float2(a);
            float inv = 1.0f / (float)max(deg_s[vl], 1);
            ob[2 * lane][vl]     = s.x + af.x * inv + bia.x;
            ob[2 * lane + 1][vl] = s.y + af.y * inv + bia.y;
        }
    }
    __syncthreads();

    for (int i = tid; i < 64 * 32; i += 256) {
        int o = i >> 5, v = i & 31;
        int gv = v0 + v;
        if (gv < VV)
            out[((size_t)b * OO + o) * VV + gv] = ob[o][v];
    }
}

extern "C" void kernel_launch(void* const* d_in, const int* in_sizes, int n_in,
                              void* d_out, int out_size) {
    const float* x    = (const float*)d_in[0];
    const int*   nbr  = (const int*)d_in[1];
    const int*   deg  = (const int*)d_in[2];
    const float* W    = (const float*)d_in[3];
    const float* bias = (const float*)d_in[4];
    float*       out  = (float*)d_out;

    cudaFuncSetAttribute(k1_gemm, cudaFuncAttributeMaxDynamicSharedMemorySize, SM_TOTAL);

    dim3 g1(GX, BB);
    k1_gemm<<<g1, 256, SM_TOTAL>>>(x, W);

    dim3 g2((VV + 31) / 32, BB);
    k2_gather<<<g2, 256>>>(nbr, deg, bias, out);
}

// round 9
// speedup vs baseline: 1.3429x; 1.3429x over previous
#include <cuda_runtime.h>
#include <cuda_fp16.h>
#include <cstdint>

// MeshConvPoint: B=8, C=64, V=25000, D=12, O=64
// k1 (HMMA, pipelined, single-pass fp16): Z[b,v,o'] = sum_c x_h[c,v]*W_h[o,c,k]
//   R8 post-mortem: hi/lo conversion ALU (~38M F2F/FSUB/F2FP ops ~ 72us) was the
//   k1 binder, not MMA or occupancy. Single-pass fp16 cuts conversion to one
//   packed F2FP per float pair (~12us) at +2.8e-4 RMS error (calibrated vs
//   measured 2.64e-4 for the W-side rounding). fp32 TMEM-free accumulate.
//   z0 (k=0) fp32; z1 (k=1) fp16 (128B rows, L2-resident).
// k2: out = z0 + (1/deg)*sum z1[nbr] + bias. Branch-free gathers (zero-row pad),
//   half2 accumulation, pre-scaled 32-bit offsets.

#define BB 8
#define CC 64
#define VV 25000
#define DD 12
#define OO 64
#define NT 391            // ceil(VV/64) v-tiles
#define GX 74             // k1 grid.x (74*8=592 blocks = 4/SM)

__device__ float  g_z0[(size_t)BB * VV * 64];          // 51.2 MB
__device__ __half g_z1[((size_t)BB * VV + 1) * 64];    // 25.6 MB + zero row (bss-zeroed, never written)

__device__ __forceinline__ uint32_t smem_u32(const void* p) {
    uint32_t a;
    asm("{ .reg .u64 t; cvta.to.shared.u64 t, %1; cvt.u32.u64 %0, t; }" : "=r"(a) : "l"(p));
    return a;
}
__device__ __forceinline__ void ldsm_x4_t(uint32_t& r0, uint32_t& r1, uint32_t& r2, uint32_t& r3,
                                          uint32_t addr) {
    asm volatile("ldmatrix.sync.aligned.m8n8.x4.trans.shared.b16 {%0,%1,%2,%3}, [%4];"
                 : "=r"(r0), "=r"(r1), "=r"(r2), "=r"(r3) : "r"(addr));
}
__device__ __forceinline__ void ldsm_x2(uint32_t& r0, uint32_t& r1, uint32_t addr) {
    asm volatile("ldmatrix.sync.aligned.m8n8.x2.shared.b16 {%0,%1}, [%2];"
                 : "=r"(r0), "=r"(r1) : "r"(addr));
}
__device__ __forceinline__ void mma16816(float* c, const uint32_t* a, const uint32_t* bfr) {
    asm volatile(
        "mma.sync.aligned.m16n8k16.row.col.f32.f16.f16.f32 "
        "{%0,%1,%2,%3}, {%4,%5,%6,%7}, {%8,%9}, {%0,%1,%2,%3};"
        : "+f"(c[0]), "+f"(c[1]), "+f"(c[2]), "+f"(c[3])
        : "r"(a[0]), "r"(a[1]), "r"(a[2]), "r"(a[3]), "r"(bfr[0]), "r"(bfr[1]));
}
__device__ __forceinline__ uint32_t packf2(float a, float b) {
    __half2 h = __floats2half2_rn(a, b);             // single F2FP.PACK
    return *reinterpret_cast<uint32_t*>(&h);
}

// smem layout (bytes), row stride 144 -> conflict-free ldmatrix
#define LDB    144
#define SM_BHI 0
#define SM_A0  (SM_BHI + 128 * LDB)       // 18432
#define SM_A1  (SM_A0 + 64 * LDB)         // 27648
#define SM_TOTAL (SM_A1 + 64 * LDB)       // 36864 bytes

// ---------------------------------------------------------------------------
// Kernel 1: 256 threads (8 warps, warp-grid 2m x 4n). Tile = 64v x 128o'.
// Block loops over v-tiles t = bx, bx+GX, ... with double-buffered A.
// ---------------------------------------------------------------------------
__global__ __launch_bounds__(256, 4) void k1_gemm(const float* __restrict__ x,
                                                  const float* __restrict__ W) {
    extern __shared__ char smem[];
    const uint32_t sb = smem_u32(smem);
    const int tid = threadIdx.x, wid = tid >> 5, lane = tid & 31;
    const int b = blockIdx.y, bx = blockIdx.x;
    const int mh = wid >> 2, nq = wid & 3;

    // ---- W prep (once per block): 1024 items = 128 o'-rows x 8 c-groups ----
    for (int i = tid; i < 1024; i += 256) {
        int op = i >> 3, g = i & 7;       // B-row o' = kk*64+o, c-group
        int o = op & 63, kk = op >> 6;
        const float* wp = W + ((size_t)o * 64 + g * 8) * 2 + kk;
        uint4 u;
        u.x = packf2(wp[0],  wp[2]);
        u.y = packf2(wp[4],  wp[6]);
        u.z = packf2(wp[8],  wp[10]);
        u.w = packf2(wp[12], wp[14]);
        *reinterpret_cast<uint4*>(smem + SM_BHI + (uint32_t)op * LDB + g * 16) = u;
    }

    const float* xb = x + (size_t)b * CC * VV;
    const int c  = tid >> 2;              // x row this thread loads/converts
    const int vs = (tid & 3) * 16;        // 16 v's = 4 float4

    float4 f[4];
    {
        const int v0 = bx * 64;
        #pragma unroll
        for (int j = 0; j < 4; j++) {
            int vbse = v0 + vs + 4 * j;
            f[j] = (vbse + 3 < VV) ? *reinterpret_cast<const float4*>(xb + (size_t)c * VV + vbse)
                                   : make_float4(0.f, 0.f, 0.f, 0.f);
        }
    }
    {
        uint32_t off = SM_A0 + (uint32_t)c * LDB + vs * 2;
        #pragma unroll
        for (int j = 0; j < 4; j++)
            *reinterpret_cast<uint2*>(smem + off + j * 8) =
                make_uint2(packf2(f[j].x, f[j].y), packf2(f[j].z, f[j].w));
    }

    const int r  = lane >> 2, cp = (lane & 3) * 2;
    float*  z0p = g_z0 + (size_t)b * VV * 64;
    __half* z1p = g_z1 + (size_t)b * VV * 64;

    int buf = 0;
    for (int t = bx; t < NT; t += GX) {
        __syncthreads();                  // A[buf] (and W on iter 0) visible
        const int tn = t + GX;

        // prefetch next tile's x into regs (in flight during MMA)
        if (tn < NT) {
            const int v0n = tn * 64;
            #pragma unroll
            for (int j = 0; j < 4; j++) {
                int vbse = v0n + vs + 4 * j;
                f[j] = (vbse + 3 < VV) ? *reinterpret_cast<const float4*>(xb + (size_t)c * VV + vbse)
                                       : make_float4(0.f, 0.f, 0.f, 0.f);
            }
        }

        // ---- MMA on A[buf]: single fp16 pass, K=64 in 4 steps ----
        float acc[2][4][4];
        #pragma unroll
        for (int mt = 0; mt < 2; mt++)
            #pragma unroll
            for (int nt = 0; nt < 4; nt++)
                #pragma unroll
                for (int q = 0; q < 4; q++) acc[mt][nt][q] = 0.0f;

        const uint32_t Ab = sb + (buf ? SM_A1 : SM_A0);
        const uint32_t Bb = sb + SM_BHI;
        #pragma unroll
        for (int ks = 0; ks < 4; ks++) {
            uint32_t af[2][4];
            #pragma unroll
            for (int mt = 0; mt < 2; mt++) {
                uint32_t r0, r1, r2, r3;
                uint32_t addr = Ab + (ks * 16 + (lane & 15)) * LDB
                              + (mh * 32 + mt * 16) * 2 + (lane >> 4) * 16;
                ldsm_x4_t(r0, r1, r2, r3, addr);
                af[mt][0] = r0; af[mt][1] = r2; af[mt][2] = r1; af[mt][3] = r3;
            }
            uint32_t bf[4][2];
            #pragma unroll
            for (int nt = 0; nt < 4; nt++) {
                uint32_t addr = Bb + (nq * 32 + nt * 8 + (lane & 7)) * LDB
                              + ks * 32 + ((lane >> 3) & 1) * 16;
                ldsm_x2(bf[nt][0], bf[nt][1], addr);
            }
            #pragma unroll
            for (int mt = 0; mt < 2; mt++)
                #pragma unroll
                for (int nt = 0; nt < 4; nt++)
                    mma16816(acc[mt][nt], af[mt], bf[nt]);
        }

        // fill other buffer with prefetched tile
        if (tn < NT) {
            uint32_t off = (buf ? SM_A0 : SM_A1) + (uint32_t)c * LDB + vs * 2;
            #pragma unroll
            for (int j = 0; j < 4; j++)
                *reinterpret_cast<uint2*>(smem + off + j * 8) =
                    make_uint2(packf2(f[j].x, f[j].y), packf2(f[j].z, f[j].w));
        }

        // ---- epilogue: nq 0-1 -> z0 fp32, nq 2-3 -> z1 fp16 ----
        const int v0 = t * 64;
        if (nq < 2) {
            #pragma unroll
            for (int mt = 0; mt < 2; mt++) {
                int v1 = v0 + mh * 32 + mt * 16 + r;
                #pragma unroll
                for (int nt = 0; nt < 4; nt++) {
                    int op = nq * 32 + nt * 8 + cp;
                    if (v1 < VV)
                        *reinterpret_cast<float2*>(z0p + (size_t)v1 * 64 + op) =
                            make_float2(acc[mt][nt][0], acc[mt][nt][1]);
                    if (v1 + 8 < VV)
                        *reinterpret_cast<float2*>(z0p + (size_t)(v1 + 8) * 64 + op) =
                            make_float2(acc[mt][nt][2], acc[mt][nt][3]);
                }
            }
        } else {
            #pragma unroll
            for (int mt = 0; mt < 2; mt++) {
                int v1 = v0 + mh * 32 + mt * 16 + r;
                #pragma unroll
                for (int nt = 0; nt < 4; nt++) {
                    int oo = (nq - 2) * 32 + nt * 8 + cp;
                    if (v1 < VV) {
                        __half2 h = __floats2half2_rn(acc[mt][nt][0], acc[mt][nt][1]);
                        *reinterpret_cast<__half2*>(z1p + (size_t)v1 * 64 + oo) = h;
                    }
                    if (v1 + 8 < VV) {
                        __half2 h = __floats2half2_rn(acc[mt][nt][2], acc[mt][nt][3]);
                        *reinterpret_cast<__half2*>(z1p + (size_t)(v1 + 8) * 64 + oo) = h;
                    }
                }
            }
        }
        buf ^= 1;
    }
}

// ---------------------------------------------------------------------------
// Kernel 2: 32 v per block, 256 threads. Branch-free gathers (zero-row pad),
// pre-scaled 32-bit offsets, half2 accumulation, z0 hoisted above gathers.
// ---------------------------------------------------------------------------
__global__ __launch_bounds__(256) void k2_gather(const int* __restrict__ nbr,
                                                 const int* __restrict__ deg,
                                                 const float* __restrict__ bias,
                                                 float* __restrict__ out) {
    __shared__ int   rows32[32][DD];   // safe z1 row index * 32
    __shared__ int   deg_s[32];
    __shared__ float ob[64][33];

    const int b = blockIdx.y, v0 = blockIdx.x * 32, tid = threadIdx.x;

    if (tid < 32) {
        int gv = v0 + tid;
        deg_s[tid] = (gv < VV) ? deg[(size_t)b * VV + gv] : 0;
    }
    __syncthreads();
    for (int i = tid; i < 32 * DD; i += 256) {
        int v = i / DD, d = i % DD;
        int gv = v0 + v;
        int rr = BB * VV;                                 // zero row
        if (gv < VV && d < deg_s[v])
            rr = b * VV + nbr[((size_t)b * VV + gv) * DD + d];
        rows32[v][d] = rr * 32;
    }
    __syncthreads();

    const int w = tid >> 5, lane = tid & 31;
    const __half2* z1p = reinterpret_cast<const __half2*>(g_z1);
    const float2 bia = *reinterpret_cast<const float2*>(bias + 2 * lane);

    #pragma unroll
    for (int j = 0; j < 4; j++) {
        const int vl = w * 4 + j;
        const int gv = v0 + vl;
        float2 s = make_float2(0.f, 0.f);
        if (gv < VV)                                       // hoisted: latency overlaps gathers
            s = *reinterpret_cast<const float2*>(g_z0 + ((size_t)b * VV + gv) * 64 + 2 * lane);
        __half2 a = __halves2half2(__ushort_as_half(0), __ushort_as_half(0));
        #pragma unroll
        for (int d = 0; d < DD; d++) {
            int off = rows32[vl][d] + lane;               // IADD
            a = __hadd2(a, z1p[off]);                     // 128B coalesced/warp
        }
        if (gv < VV) {
            float2 af = __half22float2(a);
            float inv = 1.0f / (float)max(deg_s[vl], 1);
            ob[2 * lane][vl]     = s.x + af.x * inv + bia.x;
            ob[2 * lane + 1][vl] = s.y + af.y * inv + bia.y;
        }
    }
    __syncthreads();

    for (int i = tid; i < 64 * 32; i += 256) {
        int o = i >> 5, v = i & 31;
        int gv = v0 + v;
        if (gv < VV)
            out[((size_t)b * OO + o) * VV + gv] = ob[o][v];
    }
}

extern "C" void kernel_launch(void* const* d_in, const int* in_sizes, int n_in,
                              void* d_out, int out_size) {
    const float* x    = (const float*)d_in[0];
    const int*   nbr  = (const int*)d_in[1];
    const int*   deg  = (const int*)d_in[2];
    const float* W    = (const float*)d_in[3];
    const float* bias = (const float*)d_in[4];
    float*       out  = (float*)d_out;

    cudaFuncSetAttribute(k1_gemm, cudaFuncAttributeMaxDynamicSharedMemorySize, SM_TOTAL);

    dim3 g1(GX, BB);
    k1_gemm<<<g1, 256, SM_TOTAL>>>(x, W);

    dim3 g2((VV + 31) / 32, BB);
    k2_gather<<<g2, 256>>>(nbr, deg, bias, out);
}